// round 15
// baseline (speedup 1.0000x reference)
#include <cuda_runtime.h>
#include <cstdint>

#define N_TOKENS 8192
#define D_MODEL  1024
#define N_EXPERTS 8

#define TM 128            // token rows per CTA tile
#define TN 256            // output cols per CTA tile
#define TK 32             // k per SMEM stage
#define NT_MAX (2 * N_TOKENS / TM + N_EXPERTS)   // 136
#define NSTAGE 3

#define A_STRIDE 36       // words per A row (conflict-free: g*4+q perm mod 32)
#define B_STRIDE 264      // words per B k-row (264 mod 32 = 8 -> q*8+g perm mod 32)
#define A_WORDS (TM * A_STRIDE)        // 4608
#define B_WORDS (TK * B_STRIDE)        // 8448
#define STAGE_WORDS (A_WORDS + B_WORDS)
#define SMEM_DYN_BYTES (NSTAGE * STAGE_WORDS * 4)   // 156672

// ---------------- device scratch ----------------
__device__ int      g_expert[2 * N_TOKENS];
__device__ float    g_gate[2 * N_TOKENS];
__device__ int      g_perm_token[2 * N_TOKENS];
__device__ float    g_perm_gate[2 * N_TOKENS];
__device__ int      g_cursor[N_EXPERTS];
__device__ int      g_tile_expert[NT_MAX];
__device__ int      g_tile_row[NT_MAX];
__device__ int      g_tile_cnt[NT_MAX];
__device__ int      g_ntiles;
__device__ __align__(16) uint32_t g_xt[N_TOKENS * D_MODEL];   // 32MB x in tf32 bits

// ---------------- helpers ----------------
__device__ __forceinline__ uint32_t to_tf32(float f) {
    uint32_t u;
    asm("cvt.rna.tf32.f32 %0, %1;" : "=r"(u) : "f"(f));
    return u;
}
__device__ __forceinline__ uint32_t tf32_of_bits(uint32_t w) {
    return to_tf32(__uint_as_float(w));
}
__device__ __forceinline__ void mma_tf32(float* c, const uint32_t* a, const uint32_t* b) {
    asm volatile(
        "mma.sync.aligned.m16n8k8.row.col.f32.tf32.tf32.f32 "
        "{%0,%1,%2,%3}, {%4,%5,%6,%7}, {%8,%9}, {%0,%1,%2,%3};"
        : "+f"(c[0]), "+f"(c[1]), "+f"(c[2]), "+f"(c[3])
        : "r"(a[0]), "r"(a[1]), "r"(a[2]), "r"(a[3]), "r"(b[0]), "r"(b[1]));
}
__device__ __forceinline__ uint32_t smem_u32(const void* p) {
    uint32_t a;
    asm("{ .reg .u64 t; cvta.to.shared.u64 t, %1; cvt.u32.u64 %0, t; }" : "=r"(a) : "l"(p));
    return a;
}
#define CP_ASYNC16(dst, src) \
    asm volatile("cp.async.cg.shared.global [%0], [%1], 16;" :: "r"(dst), "l"(src) : "memory")
#define CP_COMMIT() asm volatile("cp.async.commit_group;" ::: "memory")
#define CP_WAIT(n)  asm volatile("cp.async.wait_group %0;" :: "n"(n) : "memory")

// ---------------- 1) router: 2 tokens/warp, vectorized Wr; + zero out -------
__global__ void router_kernel(const float* __restrict__ x,
                              const float* __restrict__ Wr,
                              const float* __restrict__ br,
                              float4* __restrict__ out4) {
    {
        int g = blockIdx.x * blockDim.x + threadIdx.x;
#pragma unroll
        for (int r = 0; r < 16; r++)
            out4[g + r * (512 * 256)] = make_float4(0.f, 0.f, 0.f, 0.f);
    }

    int warp = (blockIdx.x * blockDim.x + threadIdx.x) >> 5;   // 0..4095
    int lane = threadIdx.x & 31;
    int t0 = warp * 2, t1 = t0 + 1;
    const float* x0 = x + (size_t)t0 * D_MODEL;
    const float* x1 = x + (size_t)t1 * D_MODEL;
    uint32_t* xt0 = g_xt + (size_t)t0 * D_MODEL;
    uint32_t* xt1 = g_xt + (size_t)t1 * D_MODEL;

    float acc0[N_EXPERTS], acc1[N_EXPERTS];
#pragma unroll
    for (int e = 0; e < N_EXPERTS; e++) { acc0[e] = 0.f; acc1[e] = 0.f; }

#pragma unroll
    for (int it = 0; it < 8; it++) {
        int d = lane * 4 + it * 128;
        float4 a0 = *reinterpret_cast<const float4*>(x0 + d);
        float4 a1 = *reinterpret_cast<const float4*>(x1 + d);
        uint4 u0, u1;
        u0.x = to_tf32(a0.x); u0.y = to_tf32(a0.y); u0.z = to_tf32(a0.z); u0.w = to_tf32(a0.w);
        u1.x = to_tf32(a1.x); u1.y = to_tf32(a1.y); u1.z = to_tf32(a1.z); u1.w = to_tf32(a1.w);
        *reinterpret_cast<uint4*>(xt0 + d) = u0;
        *reinterpret_cast<uint4*>(xt1 + d) = u1;

        const float* av0 = reinterpret_cast<const float*>(&a0);
        const float* av1 = reinterpret_cast<const float*>(&a1);
#pragma unroll
        for (int r = 0; r < 4; r++) {
            float4 wlo = *reinterpret_cast<const float4*>(Wr + (size_t)(d + r) * N_EXPERTS);
            float4 whi = *reinterpret_cast<const float4*>(Wr + (size_t)(d + r) * N_EXPERTS + 4);
            float xa = av0[r], xb = av1[r];
            acc0[0] += xa * wlo.x; acc0[1] += xa * wlo.y;
            acc0[2] += xa * wlo.z; acc0[3] += xa * wlo.w;
            acc0[4] += xa * whi.x; acc0[5] += xa * whi.y;
            acc0[6] += xa * whi.z; acc0[7] += xa * whi.w;
            acc1[0] += xb * wlo.x; acc1[1] += xb * wlo.y;
            acc1[2] += xb * wlo.z; acc1[3] += xb * wlo.w;
            acc1[4] += xb * whi.x; acc1[5] += xb * whi.y;
            acc1[6] += xb * whi.z; acc1[7] += xb * whi.w;
        }
    }
#pragma unroll
    for (int off = 16; off > 0; off >>= 1) {
#pragma unroll
        for (int e = 0; e < N_EXPERTS; e++) {
            acc0[e] += __shfl_xor_sync(0xffffffffu, acc0[e], off);
            acc1[e] += __shfl_xor_sync(0xffffffffu, acc1[e], off);
        }
    }
    if (lane == 0) {
#pragma unroll
        for (int t = 0; t < 2; t++) {
            float* acc = t ? acc1 : acc0;
            int tok = t ? t1 : t0;
#pragma unroll
            for (int e = 0; e < N_EXPERTS; e++) acc[e] += br[e];
            int e0 = 0; float v0 = acc[0];
#pragma unroll
            for (int e = 1; e < N_EXPERTS; e++) if (acc[e] > v0) { v0 = acc[e]; e0 = e; }
            int e1 = -1; float v1 = -3.4e38f;
#pragma unroll
            for (int e = 0; e < N_EXPERTS; e++)
                if (e != e0 && acc[e] > v1) { v1 = acc[e]; e1 = e; }
            float g0 = 1.f / (1.f + __expf(v1 - v0));
            float g1 = 1.f - g0;
            g_expert[2 * tok + 0] = e0;  g_gate[2 * tok + 0] = g0;
            g_expert[2 * tok + 1] = e1;  g_gate[2 * tok + 1] = g1;
        }
    }
}

// ---------------- 2) build tiles (1 block; register histogram) ----------
__global__ void build_tiles_kernel() {
    __shared__ int s_cnt[N_EXPERTS];
    int tid = threadIdx.x;
    if (tid < N_EXPERTS) s_cnt[tid] = 0;
    __syncthreads();

    int loc[N_EXPERTS];
#pragma unroll
    for (int e = 0; e < N_EXPERTS; e++) loc[e] = 0;
    for (int i = tid; i < 2 * N_TOKENS; i += blockDim.x) {
        int e = g_expert[i];
#pragma unroll
        for (int k = 0; k < N_EXPERTS; k++) loc[k] += (e == k);
    }
#pragma unroll
    for (int e = 0; e < N_EXPERTS; e++)
        if (loc[e]) atomicAdd(&s_cnt[e], loc[e]);
    __syncthreads();

    if (tid == 0) {
        int o = 0, nt = 0;
        for (int e = 0; e < N_EXPERTS; e++) {
            g_cursor[e] = o;
            int c = s_cnt[e];
            for (int t = 0; t < c; t += TM) {
                g_tile_expert[nt] = e;
                g_tile_row[nt]    = o + t;
                g_tile_cnt[nt]    = (c - t < TM) ? (c - t) : TM;
                nt++;
            }
            o += c;
        }
        g_ntiles = nt;
    }
}

// ---------------- 3) scatter: warp-aggregated atomics ----------------
__global__ void scatter_kernel() {
    int i = blockIdx.x * 256 + threadIdx.x;       // 0..16383
    int lane = threadIdx.x & 31;
    int e = g_expert[i];
    float g = g_gate[i];
    int pos = 0;
#pragma unroll
    for (int k = 0; k < N_EXPERTS; k++) {
        unsigned m = __ballot_sync(0xffffffffu, e == k);
        if (e == k) {
            int leader = __ffs(m) - 1;
            int base = 0;
            if (lane == leader) base = atomicAdd(&g_cursor[k], __popc(m));
            base = __shfl_sync(m, base, leader);
            pos = base + __popc(m & ((1u << lane) - 1));
        }
    }
    g_perm_token[pos] = i >> 1;
    g_perm_gate[pos]  = g;
}

// ---------------- 4) tf32 mma.sync grouped GEMM, cp.async 3-stage ----------
// CTA 128x256, 8 warps 2(M)x4(N), warp tile 64x64, m16n8k8.
// A pre-converted tf32 bits (g_xt); B raw fp32 in SMEM, cvt.rna at frag load.
__global__ __launch_bounds__(256, 1)
void moe_gemm_mma(const float* __restrict__ W, const float* __restrict__ bias,
                  float* __restrict__ out) {
    extern __shared__ uint32_t dyn[];
    __shared__ int   s_tok[TM];
    __shared__ float s_gate[TM];
    __shared__ float s_bias[TN];

    int tile = blockIdx.x;
    if (tile >= g_ntiles) return;

    int e    = g_tile_expert[tile];
    int row0 = g_tile_row[tile];
    int mcnt = g_tile_cnt[tile];
    int h0   = blockIdx.y * TN;
    int tid  = threadIdx.x;
    int wid  = tid >> 5;
    int lane = tid & 31;
    int warp_m = wid & 1;     // 0..1 -> 64 rows
    int warp_n = wid >> 1;    // 0..3 -> 64 cols

    if (tid < TM) {
        int src = row0 + ((tid < mcnt) ? tid : (mcnt - 1));
        s_tok[tid]  = g_perm_token[src];
        s_gate[tid] = (tid < mcnt) ? g_perm_gate[src] : 0.f;
    }
    s_bias[tid] = bias[(size_t)e * D_MODEL + h0 + tid];
    __syncthreads();

    // ---- per-thread fixed load coordinates (16B chunks = 4 words) ----
    // A: 128 rows x 32 k = 1024 chunks -> 4 per thread (as R10)
    int a_m    = tid >> 1;
    int a_koff = (tid & 1) * 16;
    const uint32_t* a_src = g_xt + (size_t)s_tok[a_m] * D_MODEL + a_koff;
    // B: 32 k-rows x 256 floats = 2048 chunks -> 8 per thread
    int b_k = tid >> 3;                     // 0..31
    int b_h = (tid & 7) * 4;                // word offset within 256-float row
    const float* b_src = W + (size_t)e * D_MODEL * D_MODEL
                           + (size_t)b_k * D_MODEL + h0 + b_h;

    auto issue_stage = [&](int buf, int k0) {
        uint32_t* As = dyn + buf * STAGE_WORDS;
        uint32_t* Bs = As + A_WORDS;
        uint32_t ad = smem_u32(&As[a_m * A_STRIDE + a_koff]);
#pragma unroll
        for (int c = 0; c < 4; c++)
            CP_ASYNC16(ad + c * 16, a_src + k0 + c * 4);
        uint32_t bd = smem_u32(&Bs[b_k * B_STRIDE + b_h]);
#pragma unroll
        for (int c = 0; c < 8; c++)
            CP_ASYNC16(bd + c * 128, b_src + (size_t)k0 * D_MODEL + c * 32);
    };

    float acc[4][8][4];
#pragma unroll
    for (int i = 0; i < 4; i++)
#pragma unroll
        for (int j = 0; j < 8; j++)
#pragma unroll
            for (int c = 0; c < 4; c++) acc[i][j][c] = 0.f;

    auto compute_stage = [&](int buf) {
        const uint32_t* As = dyn + buf * STAGE_WORDS;
        const uint32_t* Bs = As + A_WORDS;
#pragma unroll
        for (int ks = 0; ks < 4; ks++) {
            int kk = ks * 8;
            uint32_t a[4][4];
#pragma unroll
            for (int i = 0; i < 4; i++) {
                int r = warp_m * 64 + i * 16 + (lane >> 2);
                int c = kk + (lane & 3);
                a[i][0] = As[r * A_STRIDE + c];
                a[i][1] = As[(r + 8) * A_STRIDE + c];
                a[i][2] = As[r * A_STRIDE + c + 4];
                a[i][3] = As[(r + 8) * A_STRIDE + c + 4];
            }
            uint32_t b[8][2];
#pragma unroll
            for (int j = 0; j < 8; j++) {
                int n = warp_n * 64 + j * 8 + (lane >> 2);
                int k = kk + (lane & 3);
                b[j][0] = tf32_of_bits(Bs[k * B_STRIDE + n]);
                b[j][1] = tf32_of_bits(Bs[(k + 4) * B_STRIDE + n]);
            }
#pragma unroll
            for (int i = 0; i < 4; i++)
#pragma unroll
                for (int j = 0; j < 8; j++)
                    mma_tf32(acc[i][j], a[i], b[j]);
        }
    };

    issue_stage(0, 0);  CP_COMMIT();
    issue_stage(1, TK); CP_COMMIT();

    const int NIT = D_MODEL / TK;   // 32
#pragma unroll 1
    for (int it = 0; it < NIT; it++) {
        if (it >= NIT - 2) CP_WAIT(0); else CP_WAIT(1);
        __syncthreads();
        // safe: passing the sync means every warp finished compute(it-1),
        // the last consumer of buffer (it+2)%NSTAGE.
        if (it + 2 < NIT) { issue_stage((it + 2) % NSTAGE, (it + 2) * TK); CP_COMMIT(); }
        compute_stage(it % NSTAGE);
    }

    // ---- epilogue: out[token] += gate*(acc + bias); exactly 2 adds/element --
#pragma unroll
    for (int i = 0; i < 4; i++) {
        int m0 = warp_m * 64 + i * 16 + (lane >> 2);
        int m1 = m0 + 8;
        float ga = s_gate[m0], gb = s_gate[m1];
        float* o0 = out + (size_t)s_tok[m0] * D_MODEL + h0;
        float* o1 = out + (size_t)s_tok[m1] * D_MODEL + h0;
        bool v0 = (m0 < mcnt), v1 = (m1 < mcnt);
#pragma unroll
        for (int j = 0; j < 8; j++) {
            int c = warp_n * 64 + j * 8 + 2 * (lane & 3);
            if (v0) {
                atomicAdd(o0 + c,     ga * (acc[i][j][0] + s_bias[c]));
                atomicAdd(o0 + c + 1, ga * (acc[i][j][1] + s_bias[c + 1]));
            }
            if (v1) {
                atomicAdd(o1 + c,     gb * (acc[i][j][2] + s_bias[c]));
                atomicAdd(o1 + c + 1, gb * (acc[i][j][3] + s_bias[c + 1]));
            }
        }
    }
}

// ---------------- launcher ----------------
extern "C" void kernel_launch(void* const* d_in, const int* in_sizes, int n_in,
                              void* d_out, int out_size) {
    const float* x  = (const float*)d_in[0];
    const float* Wr = (const float*)d_in[1];
    const float* br = (const float*)d_in[2];
    const float* W  = (const float*)d_in[3];
    const float* b  = (const float*)d_in[4];
    float* out = (float*)d_out;

    static bool attr_done = false;
    if (!attr_done) {
        cudaFuncSetAttribute(moe_gemm_mma, cudaFuncAttributeMaxDynamicSharedMemorySize,
                             SMEM_DYN_BYTES);
        attr_done = true;
    }

    router_kernel<<<512, 256>>>(x, Wr, br, (float4*)out);   // launch 1
    build_tiles_kernel<<<1, 256>>>();                       // launch 2
    scatter_kernel<<<64, 256>>>();                          // launch 3

    dim3 grid(NT_MAX, D_MODEL / TN);                        // 136 x 4
    moe_gemm_mma<<<grid, 256, SMEM_DYN_BYTES>>>(W, b, out); // launch 4 (profiled)
}

// round 17
// speedup vs baseline: 1.5304x; 1.5304x over previous
#include <cuda_runtime.h>
#include <cuda_fp16.h>
#include <cstdint>

#define N_TOKENS 8192
#define D_MODEL  1024
#define N_EXPERTS 8

#define TM 128            // token rows per CTA tile
#define TN 128            // output cols per CTA tile
#define TK 32             // k per SMEM stage
#define NT_MAX (2 * N_TOKENS / TM + N_EXPERTS)   // 136
#define NSTAGE 3

#define AH_STRIDE 40      // halves per A row (80B; frag banks 20r+{0..3} = perm)
#define BH_STRIDE 40      // halves per B n-row (same layout)
#define A_HALVES (TM * AH_STRIDE)      // 5120
#define B_HALVES (TN * BH_STRIDE)      // 5120
#define STAGE_HALVES (A_HALVES + B_HALVES)
#define SMEM_DYN_BYTES (NSTAGE * STAGE_HALVES * 2)   // 61440

// ---------------- device scratch ----------------
__device__ int      g_expert[2 * N_TOKENS];
__device__ float    g_gate[2 * N_TOKENS];
__device__ int      g_perm_token[2 * N_TOKENS];
__device__ float    g_perm_gate[2 * N_TOKENS];
__device__ int      g_cursor[N_EXPERTS];
__device__ int      g_tile_expert[NT_MAX];
__device__ int      g_tile_row[NT_MAX];
__device__ int      g_tile_cnt[NT_MAX];
__device__ int      g_ntiles;
__device__ __align__(16) __half g_xh[N_TOKENS * D_MODEL];              // 16MB x fp16
__device__ __align__(16) __half g_wh[(size_t)N_EXPERTS * D_MODEL * D_MODEL]; // 16MB W^T fp16 [e][h][k]

// ---------------- helpers ----------------
__device__ __forceinline__ void mma_f16(float* c, const uint32_t* a, const uint32_t* b) {
    asm volatile(
        "mma.sync.aligned.m16n8k16.row.col.f32.f16.f16.f32 "
        "{%0,%1,%2,%3}, {%4,%5,%6,%7}, {%8,%9}, {%0,%1,%2,%3};"
        : "+f"(c[0]), "+f"(c[1]), "+f"(c[2]), "+f"(c[3])
        : "r"(a[0]), "r"(a[1]), "r"(a[2]), "r"(a[3]), "r"(b[0]), "r"(b[1]));
}
__device__ __forceinline__ uint32_t smem_u32(const void* p) {
    uint32_t a;
    asm("{ .reg .u64 t; cvta.to.shared.u64 t, %1; cvt.u32.u64 %0, t; }" : "=r"(a) : "l"(p));
    return a;
}
#define CP_ASYNC16(dst, src) \
    asm volatile("cp.async.cg.shared.global [%0], [%1], 16;" :: "r"(dst), "l"(src) : "memory")
#define CP_COMMIT() asm volatile("cp.async.commit_group;" ::: "memory")
#define CP_WAIT(n)  asm volatile("cp.async.wait_group %0;" :: "n"(n) : "memory")

// ---------------- 1) router: 2 tokens/warp, vectorized Wr; x->fp16; zero out
__global__ void router_kernel(const float* __restrict__ x,
                              const float* __restrict__ Wr,
                              const float* __restrict__ br,
                              float4* __restrict__ out4) {
    {
        int g = blockIdx.x * blockDim.x + threadIdx.x;
#pragma unroll
        for (int r = 0; r < 16; r++)
            out4[g + r * (512 * 256)] = make_float4(0.f, 0.f, 0.f, 0.f);
    }

    int warp = (blockIdx.x * blockDim.x + threadIdx.x) >> 5;   // 0..4095
    int lane = threadIdx.x & 31;
    int t0 = warp * 2, t1 = t0 + 1;
    const float* x0 = x + (size_t)t0 * D_MODEL;
    const float* x1 = x + (size_t)t1 * D_MODEL;
    __half* xh0 = g_xh + (size_t)t0 * D_MODEL;
    __half* xh1 = g_xh + (size_t)t1 * D_MODEL;

    float acc0[N_EXPERTS], acc1[N_EXPERTS];
#pragma unroll
    for (int e = 0; e < N_EXPERTS; e++) { acc0[e] = 0.f; acc1[e] = 0.f; }

#pragma unroll
    for (int it = 0; it < 8; it++) {
        int d = lane * 4 + it * 128;
        float4 a0 = *reinterpret_cast<const float4*>(x0 + d);
        float4 a1 = *reinterpret_cast<const float4*>(x1 + d);
        __half2 p00 = __floats2half2_rn(a0.x, a0.y);
        __half2 p01 = __floats2half2_rn(a0.z, a0.w);
        __half2 p10 = __floats2half2_rn(a1.x, a1.y);
        __half2 p11 = __floats2half2_rn(a1.z, a1.w);
        *reinterpret_cast<__half2*>(xh0 + d)     = p00;
        *reinterpret_cast<__half2*>(xh0 + d + 2) = p01;
        *reinterpret_cast<__half2*>(xh1 + d)     = p10;
        *reinterpret_cast<__half2*>(xh1 + d + 2) = p11;

        const float* av0 = reinterpret_cast<const float*>(&a0);
        const float* av1 = reinterpret_cast<const float*>(&a1);
#pragma unroll
        for (int r = 0; r < 4; r++) {
            float4 wlo = *reinterpret_cast<const float4*>(Wr + (size_t)(d + r) * N_EXPERTS);
            float4 whi = *reinterpret_cast<const float4*>(Wr + (size_t)(d + r) * N_EXPERTS + 4);
            float xa = av0[r], xb = av1[r];
            acc0[0] += xa * wlo.x; acc0[1] += xa * wlo.y;
            acc0[2] += xa * wlo.z; acc0[3] += xa * wlo.w;
            acc0[4] += xa * whi.x; acc0[5] += xa * whi.y;
            acc0[6] += xa * whi.z; acc0[7] += xa * whi.w;
            acc1[0] += xb * wlo.x; acc1[1] += xb * wlo.y;
            acc1[2] += xb * wlo.z; acc1[3] += xb * wlo.w;
            acc1[4] += xb * whi.x; acc1[5] += xb * whi.y;
            acc1[6] += xb * whi.z; acc1[7] += xb * whi.w;
        }
    }
#pragma unroll
    for (int off = 16; off > 0; off >>= 1) {
#pragma unroll
        for (int e = 0; e < N_EXPERTS; e++) {
            acc0[e] += __shfl_xor_sync(0xffffffffu, acc0[e], off);
            acc1[e] += __shfl_xor_sync(0xffffffffu, acc1[e], off);
        }
    }
    if (lane == 0) {
#pragma unroll
        for (int t = 0; t < 2; t++) {
            float* acc = t ? acc1 : acc0;
            int tok = t ? t1 : t0;
#pragma unroll
            for (int e = 0; e < N_EXPERTS; e++) acc[e] += br[e];
            int e0 = 0; float v0 = acc[0];
#pragma unroll
            for (int e = 1; e < N_EXPERTS; e++) if (acc[e] > v0) { v0 = acc[e]; e0 = e; }
            int e1 = -1; float v1 = -3.4e38f;
#pragma unroll
            for (int e = 0; e < N_EXPERTS; e++)
                if (e != e0 && acc[e] > v1) { v1 = acc[e]; e1 = e; }
            float g0 = 1.f / (1.f + __expf(v1 - v0));
            float g1 = 1.f - g0;
            g_expert[2 * tok + 0] = e0;  g_gate[2 * tok + 0] = g0;
            g_expert[2 * tok + 1] = e1;  g_gate[2 * tok + 1] = g1;
        }
    }
}

// ---------------- 2) build tiles (1 block; register histogram) ----------
__global__ void build_tiles_kernel() {
    __shared__ int s_cnt[N_EXPERTS];
    int tid = threadIdx.x;
    if (tid < N_EXPERTS) s_cnt[tid] = 0;
    __syncthreads();

    int loc[N_EXPERTS];
#pragma unroll
    for (int e = 0; e < N_EXPERTS; e++) loc[e] = 0;
    for (int i = tid; i < 2 * N_TOKENS; i += blockDim.x) {
        int e = g_expert[i];
#pragma unroll
        for (int k = 0; k < N_EXPERTS; k++) loc[k] += (e == k);
    }
#pragma unroll
    for (int e = 0; e < N_EXPERTS; e++)
        if (loc[e]) atomicAdd(&s_cnt[e], loc[e]);
    __syncthreads();

    if (tid == 0) {
        int o = 0, nt = 0;
        for (int e = 0; e < N_EXPERTS; e++) {
            g_cursor[e] = o;
            int c = s_cnt[e];
            for (int t = 0; t < c; t += TM) {
                g_tile_expert[nt] = e;
                g_tile_row[nt]    = o + t;
                g_tile_cnt[nt]    = (c - t < TM) ? (c - t) : TM;
                nt++;
            }
            o += c;
        }
        g_ntiles = nt;
    }
}

// ---------------- 3) scatter (blocks 0..63) + W -> fp16 transpose ----------
// g_wh[e][h][k] = fp16(W[e][k][h]); 32x32 tiles, 8192 transpose blocks.
__global__ void scatter_wtrans_kernel(const float* __restrict__ W) {
    __shared__ __half tile[32][34];
    if (blockIdx.x < 64) {
        int i = blockIdx.x * 256 + threadIdx.x;       // 0..16383
        int lane = threadIdx.x & 31;
        int e = g_expert[i];
        float g = g_gate[i];
        int pos = 0;
#pragma unroll
        for (int k = 0; k < N_EXPERTS; k++) {
            unsigned m = __ballot_sync(0xffffffffu, e == k);
            if (e == k) {
                int leader = __ffs(m) - 1;
                int base = 0;
                if (lane == leader) base = atomicAdd(&g_cursor[k], __popc(m));
                base = __shfl_sync(m, base, leader);
                pos = base + __popc(m & ((1u << lane) - 1));
            }
        }
        g_perm_token[pos] = i >> 1;
        g_perm_gate[pos]  = g;
    } else {
        int bi = blockIdx.x - 64;              // 0..8191
        int e  = bi >> 10;                     // 1024 tiles per expert
        int rem = bi & 1023;
        int th = rem >> 5, tk = rem & 31;
        int k0 = tk * 32, h0 = th * 32;
        int tx = threadIdx.x & 31, ty = threadIdx.x >> 5;   // 32 x 8
        const float* Wp = W + ((size_t)e << 20);
#pragma unroll
        for (int i = 0; i < 4; i++) {
            int k = k0 + ty + i * 8;
            tile[ty + i * 8][tx] = __float2half_rn(Wp[(size_t)k * D_MODEL + h0 + tx]);
        }
        __syncthreads();
        __half* dst = g_wh + ((size_t)e << 20);
#pragma unroll
        for (int i = 0; i < 4; i++) {
            int h = h0 + ty + i * 8;
            dst[(size_t)h * D_MODEL + k0 + tx] = tile[tx][ty + i * 8];
        }
    }
}

// ---------------- 4) fp16 mma.sync grouped GEMM, cp.async 3-stage ----------
// CTA 128x128, 8 warps 2(M)x4(N), warp tile 64x32, m16n8k16 fp16, fp32 acc.
// A: g_xh [tok][k]; B: g_wh [e][h][k] (col-major for mma). Conflict-free 80B rows.
__global__ __launch_bounds__(256, 2)
void moe_gemm_mma(const float* __restrict__ bias, float* __restrict__ out) {
    extern __shared__ __half dynh[];
    __shared__ int   s_tok[TM];
    __shared__ float s_gate[TM];
    __shared__ float s_bias[TN];

    int tile = blockIdx.x;
    if (tile >= g_ntiles) return;

    int e    = g_tile_expert[tile];
    int row0 = g_tile_row[tile];
    int mcnt = g_tile_cnt[tile];
    int h0   = blockIdx.y * TN;
    int tid  = threadIdx.x;
    int wid  = tid >> 5;
    int lane = tid & 31;
    int warp_m = wid & 1;
    int warp_n = wid >> 1;

    if (tid < TM) {
        int src = row0 + ((tid < mcnt) ? tid : (mcnt - 1));
        s_tok[tid]  = g_perm_token[src];
        s_gate[tid] = (tid < mcnt) ? g_perm_gate[src] : 0.f;
    }
    if (tid < TN) s_bias[tid] = bias[(size_t)e * D_MODEL + h0 + tid];
    __syncthreads();

    // per-thread fixed load coordinates: 2 chunks A + 2 chunks B (16B = 8 halves)
    int a_m    = tid >> 1;                    // 0..127
    int a_koff = (tid & 1) * 16;              // halves
    const __half* a_src = g_xh + (size_t)s_tok[a_m] * D_MODEL + a_koff;
    int b_n    = tid >> 1;                    // 0..127 (n-rows)
    int b_koff = (tid & 1) * 16;
    const __half* b_src = g_wh + ((size_t)e << 20)
                        + (size_t)(h0 + b_n) * D_MODEL + b_koff;

    auto issue_stage = [&](int buf, int k0) {
        __half* As = dynh + buf * STAGE_HALVES;
        __half* Bs = As + A_HALVES;
        uint32_t ad = smem_u32(&As[a_m * AH_STRIDE + a_koff]);
        CP_ASYNC16(ad,      a_src + k0);
        CP_ASYNC16(ad + 16, a_src + k0 + 8);
        uint32_t bd = smem_u32(&Bs[b_n * BH_STRIDE + b_koff]);
        CP_ASYNC16(bd,      b_src + k0);
        CP_ASYNC16(bd + 16, b_src + k0 + 8);
    };

    float acc[4][4][4];
#pragma unroll
    for (int i = 0; i < 4; i++)
#pragma unroll
        for (int j = 0; j < 4; j++)
#pragma unroll
            for (int c = 0; c < 4; c++) acc[i][j][c] = 0.f;

    auto compute_stage = [&](int buf) {
        const __half* As = dynh + buf * STAGE_HALVES;
        const __half* Bs = As + A_HALVES;
#pragma unroll
        for (int ks = 0; ks < 2; ks++) {          // 2 x k16 per 32-k stage
            int kk = ks * 16;
            int c = kk + (lane & 3) * 2;
            uint32_t a[4][4];
#pragma unroll
            for (int i = 0; i < 4; i++) {
                int r = warp_m * 64 + i * 16 + (lane >> 2);
                a[i][0] = *reinterpret_cast<const uint32_t*>(&As[r * AH_STRIDE + c]);
                a[i][1] = *reinterpret_cast<const uint32_t*>(&As[(r + 8) * AH_STRIDE + c]);
                a[i][2] = *reinterpret_cast<const uint32_t*>(&As[r * AH_STRIDE + c + 8]);
                a[i][3] = *reinterpret_cast<const uint32_t*>(&As[(r + 8) * AH_STRIDE + c + 8]);
            }
            uint32_t b[4][2];
#pragma unroll
            for (int j = 0; j < 4; j++) {
                int n = warp_n * 32 + j * 8 + (lane >> 2);
                b[j][0] = *reinterpret_cast<const uint32_t*>(&Bs[n * BH_STRIDE + c]);
                b[j][1] = *reinterpret_cast<const uint32_t*>(&Bs[n * BH_STRIDE + c + 8]);
            }
#pragma unroll
            for (int i = 0; i < 4; i++)
#pragma unroll
                for (int j = 0; j < 4; j++)
                    mma_f16(acc[i][j], a[i], b[j]);
        }
    };

    issue_stage(0, 0);  CP_COMMIT();
    issue_stage(1, TK); CP_COMMIT();

    const int NIT = D_MODEL / TK;   // 32
#pragma unroll 1
    for (int it = 0; it < NIT; it++) {
        if (it >= NIT - 2) CP_WAIT(0); else CP_WAIT(1);
        __syncthreads();
        // safe: passing the sync means every warp finished compute(it-1),
        // the last consumer of buffer (it+2)%NSTAGE.
        if (it + 2 < NIT) { issue_stage((it + 2) % NSTAGE, (it + 2) * TK); CP_COMMIT(); }
        compute_stage(it % NSTAGE);
    }

    // ---- epilogue: out[token] += gate*(acc + bias); exactly 2 adds/element --
#pragma unroll
    for (int i = 0; i < 4; i++) {
        int m0 = warp_m * 64 + i * 16 + (lane >> 2);
        int m1 = m0 + 8;
        float ga = s_gate[m0], gb = s_gate[m1];
        float* o0 = out + (size_t)s_tok[m0] * D_MODEL + h0;
        float* o1 = out + (size_t)s_tok[m1] * D_MODEL + h0;
        bool v0 = (m0 < mcnt), v1 = (m1 < mcnt);
#pragma unroll
        for (int j = 0; j < 4; j++) {
            int c = warp_n * 32 + j * 8 + 2 * (lane & 3);
            if (v0) {
                atomicAdd(o0 + c,     ga * (acc[i][j][0] + s_bias[c]));
                atomicAdd(o0 + c + 1, ga * (acc[i][j][1] + s_bias[c + 1]));
            }
            if (v1) {
                atomicAdd(o1 + c,     gb * (acc[i][j][2] + s_bias[c]));
                atomicAdd(o1 + c + 1, gb * (acc[i][j][3] + s_bias[c + 1]));
            }
        }
    }
}

// ---------------- launcher ----------------
extern "C" void kernel_launch(void* const* d_in, const int* in_sizes, int n_in,
                              void* d_out, int out_size) {
    const float* x  = (const float*)d_in[0];
    const float* Wr = (const float*)d_in[1];
    const float* br = (const float*)d_in[2];
    const float* W  = (const float*)d_in[3];
    const float* b  = (const float*)d_in[4];
    float* out = (float*)d_out;

    static bool attr_done = false;
    if (!attr_done) {
        cudaFuncSetAttribute(moe_gemm_mma, cudaFuncAttributeMaxDynamicSharedMemorySize,
                             SMEM_DYN_BYTES);
        attr_done = true;
    }

    router_kernel<<<512, 256>>>(x, Wr, br, (float4*)out);   // launch 1
    build_tiles_kernel<<<1, 256>>>();                       // launch 2
    scatter_wtrans_kernel<<<64 + 8192, 256>>>(W);           // launch 3 (scatter + W^T fp16)

    dim3 grid(NT_MAX, D_MODEL / TN);                        // 136 x 8
    moe_gemm_mma<<<grid, 256, SMEM_DYN_BYTES>>>(b, out);    // launch 4 (profiled)
}